// round 11
// baseline (speedup 1.0000x reference)
#include <cuda_runtime.h>

#define TM        4
#define NTHREADS  128
#define M_DIM     8192
#define N_DIM     8192

typedef unsigned long long u64;

// ---- packed f32x2 helpers (sm_103a) ----
__device__ __forceinline__ u64 pack2(float a, float b) {
    u64 r;
    asm("mov.b64 %0, {%1, %2};" : "=l"(r) : "f"(a), "f"(b));
    return r;
}
__device__ __forceinline__ u64 fma2(u64 a, u64 b, u64 c) {
    u64 d;
    asm("fma.rn.f32x2 %0, %1, %2, %3;" : "=l"(d) : "l"(a), "l"(b), "l"(c));
    return d;
}
__device__ __forceinline__ void unpack2(u64 v, float& a, float& b) {
    asm("mov.b64 {%0, %1}, %2;" : "=f"(a), "=f"(b) : "l"(v));
}

// y[r][m] = sum_n code[nib(m,n)] * absmax[(m*N+n)/64] * x[r][n] + bias[m]
// qweight int32 = one packed byte: hi nibble = even col, lo nibble = odd col.
//
// Half-chunk decode (4 columns at a time): q loaded as int2, x as one
// ulonglong2 pair per row -> transient regs cut ~40% vs R10, enabling
// __launch_bounds__(128,6): 24 warps/SM instead of the 16 that capped
// every previous round at ~42us.
__global__ void __launch_bounds__(NTHREADS, 6)
fp4_gemv_kernel(const float* __restrict__ x,
                const int*   __restrict__ qweight,
                const float* __restrict__ absmax,
                const float* __restrict__ code,
                const float* __restrict__ bias,
                float*       __restrict__ out)
{
    __shared__ float code_rep[16 * 32];    // [idx][lane]: bank == lane, conflict-free
    __shared__ float red[4][TM * 4];

    const int tid = threadIdx.x;
    const int w   = tid >> 5;
    const int l   = tid & 31;

    #pragma unroll
    for (int i = tid; i < 16 * 32; i += NTHREADS)
        code_rep[i] = code[i >> 5];
    __syncthreads();

    const float* __restrict__ my_tab = code_rep + l;   // this lane's bank column

    const int m0 = blockIdx.x * TM;
    const int2* __restrict__ qw2 = (const int2*)qweight;   // 2048 int2 per row

    u64 acc[TM][4];                        // [w-row][x-row] = (even,odd) sums
    #pragma unroll
    for (int mi = 0; mi < TM; ++mi)
        #pragma unroll
        for (int r = 0; r < 4; ++r) acc[mi][r] = 0ULL;

    const int lane_col = w * 32 + l;       // col4 base within each chunk of 128

    #pragma unroll 2
    for (int c = 0; c < 8; ++c) {
        const int col4 = c * 128 + lane_col;   // int4-granule index [0,1024)
        const int n0   = col4 * 8;             // first weight column
        const int amc  = col4 >> 3;            // absmax block within row

        float am[TM];
        #pragma unroll
        for (int mi = 0; mi < TM; ++mi)
            am[mi] = __ldg(&absmax[(m0 + mi) * 128 + amc]);

        #pragma unroll
        for (int h = 0; h < 2; ++h) {          // two halves of 4 columns each
            // q for this half: int2 = 2 packed bytes = 4 columns, per row
            int2 q[TM];
            #pragma unroll
            for (int mi = 0; mi < TM; ++mi)
                q[mi] = __ldg(&qw2[(m0 + mi) * 2048 + col4 * 2 + h]);

            // x pairs for this half: xp[j][r] = (x[r][nh+2j], x[r][nh+2j+1])
            const int nh = n0 + h * 4;
            u64 xp[2][4];
            #pragma unroll
            for (int r = 0; r < 4; ++r) {
                ulonglong2 a = __ldg((const ulonglong2*)(x + r * N_DIM + nh));
                xp[0][r] = a.x; xp[1][r] = a.y;
            }

            #pragma unroll
            for (int mi = 0; mi < TM; ++mi) {
                const unsigned b0 = (unsigned)q[mi].x;   // cols nh, nh+1
                const unsigned b1 = (unsigned)q[mi].y;   // cols nh+2, nh+3
                const u64 c0 = pack2(my_tab[(b0 & 0xF0u) << 1],
                                     my_tab[(b0 & 0x0Fu) << 5]);
                const u64 c1 = pack2(my_tab[(b1 & 0xF0u) << 1],
                                     my_tab[(b1 & 0x0Fu) << 5]);
                const u64 am2 = pack2(am[mi], am[mi]);
                #pragma unroll
                for (int r = 0; r < 4; ++r) {
                    u64 t = fma2(c0, xp[0][r], 0ULL);
                    t     = fma2(c1, xp[1][r], t);
                    acc[mi][r] = fma2(t, am2, acc[mi][r]);
                }
            }
        }
    }

    // ---- epilogue: halves sum (free unpack), shfl reduce, cross-warp ----
    float vals[TM * 4];
    #pragma unroll
    for (int mi = 0; mi < TM; ++mi)
        #pragma unroll
        for (int r = 0; r < 4; ++r) {
            float e, o;
            unpack2(acc[mi][r], e, o);
            vals[mi * 4 + r] = e + o;
        }
    #pragma unroll
    for (int i = 0; i < TM * 4; ++i) {
        float v = vals[i];
        v += __shfl_xor_sync(0xffffffffu, v, 16);
        v += __shfl_xor_sync(0xffffffffu, v, 8);
        v += __shfl_xor_sync(0xffffffffu, v, 4);
        v += __shfl_xor_sync(0xffffffffu, v, 2);
        v += __shfl_xor_sync(0xffffffffu, v, 1);
        vals[i] = v;
    }
    if (l == 0) {
        #pragma unroll
        for (int i = 0; i < TM * 4; ++i) red[w][i] = vals[i];
    }
    __syncthreads();

    if (tid < TM * 4) {
        float s = red[0][tid] + red[1][tid] + red[2][tid] + red[3][tid];
        const int mi = tid >> 2;
        const int r  = tid & 3;
        out[r * M_DIM + m0 + mi] = s + bias[m0 + mi];
    }
}

extern "C" void kernel_launch(void* const* d_in, const int* in_sizes, int n_in,
                              void* d_out, int out_size)
{
    const float* x       = (const float*)d_in[0];
    const int*   qweight = (const int*)  d_in[1];
    const float* absmax  = (const float*)d_in[2];
    const float* code    = (const float*)d_in[3];
    const float* bias    = (const float*)d_in[4];
    float*       out     = (float*)d_out;

    fp4_gemv_kernel<<<M_DIM / TM, NTHREADS>>>(x, qweight, absmax, code, bias, out);
}